// round 1
// baseline (speedup 1.0000x reference)
#include <cuda_runtime.h>
#include <math.h>

// ---------------- problem constants ----------------
#define BATCH   8
#define CH      256
#define HH      64
#define WW      64
#define HWSZ    (HH*WW)          // 4096
#define NTOK    (BATCH*HWSZ)     // 32768
#define HID     1024
#define NHEAD   8
#define HDIM    32

// ---------------- scratch (device globals: allowed) ----------------
__device__ float g_q [BATCH*CH*HWSZ];
__device__ float g_k [BATCH*CH*HWSZ];
__device__ float g_v [BATCH*CH*HWSZ];
__device__ float g_x [NTOK*CH];    // attention out, [tok, 256]
__device__ float g_xp[NTOK*CH];    // proj out (residual source)
__device__ float g_ln[NTOK*CH];    // layernorm out
__device__ float g_h [NTOK*HID];   // mlp hidden

// =====================================================================
// GEMM-NN for QKV:  C[o,n] = sum_k W[o,k] * X[k,n]   (per batch)
// W: [256,256] row-major.  X,C: [B][256][4096] channel-major.
// Tiles 64x64x16, 256 threads, 4x4 per thread.
// =====================================================================
__global__ void gemm_qkv(const float* __restrict__ W,
                         const float* __restrict__ X,
                         float* __restrict__ C)
{
    __shared__ float As[16][64];   // As[k][o]
    __shared__ float Bs[16][64];   // Bs[k][n]

    const int b  = blockIdx.z;
    const float* Xb = X + (size_t)b * CH * HWSZ;
    float*       Cb = C + (size_t)b * CH * HWSZ;

    const int nT = blockIdx.x * 64;
    const int oT = blockIdx.y * 64;

    const int tid = threadIdx.x;
    const int tx  = tid & 15, ty = tid >> 4;
    const int lr  = tid >> 2;            // 0..63
    const int lc  = (tid & 3) * 4;       // 0,4,8,12
    const int bk  = tid >> 4;            // 0..15
    const int bn  = (tid & 15) * 4;

    float acc[4][4] = {};

    for (int kt = 0; kt < 256; kt += 16) {
        float4 a4 = *(const float4*)&W[(oT + lr) * 256 + kt + lc];
        As[lc+0][lr] = a4.x; As[lc+1][lr] = a4.y;
        As[lc+2][lr] = a4.z; As[lc+3][lr] = a4.w;
        *(float4*)&Bs[bk][bn] =
            *(const float4*)&Xb[(size_t)(kt + bk) * HWSZ + nT + bn];
        __syncthreads();
        #pragma unroll
        for (int k = 0; k < 16; k++) {
            float4 a = *(const float4*)&As[k][ty * 4];
            float4 bb = *(const float4*)&Bs[k][tx * 4];
            float av[4] = {a.x, a.y, a.z, a.w};
            float bv[4] = {bb.x, bb.y, bb.z, bb.w};
            #pragma unroll
            for (int i = 0; i < 4; i++)
                #pragma unroll
                for (int j = 0; j < 4; j++)
                    acc[i][j] += av[i] * bv[j];
        }
        __syncthreads();
    }
    #pragma unroll
    for (int i = 0; i < 4; i++) {
        float4 o4 = make_float4(acc[i][0], acc[i][1], acc[i][2], acc[i][3]);
        *(float4*)&Cb[(size_t)(oT + ty*4 + i) * HWSZ + nT + tx*4] = o4;
    }
}

// =====================================================================
// Dilated 3x3 local attention. 1 thread = (pixel, head).
// q,k,v: [B][256][4096] channel-major. out: g_x [tok][256].
// OOB taps: logit = 0 (zero-padded unfold), v contribution = 0.
// =====================================================================
__global__ void attn_kernel(const float* __restrict__ q,
                            const float* __restrict__ k,
                            const float* __restrict__ v,
                            float* __restrict__ xo)
{
    const int b    = blockIdx.z;
    const int head = blockIdx.y;
    const int n    = blockIdx.x * 128 + threadIdx.x;   // pixel 0..4095
    const int py   = n >> 6;
    const int px   = n & 63;
    const int dil  = (head >> 1) + 1;                  // dilations 1,2,3,4

    const size_t base = ((size_t)b * CH + head * HDIM) * HWSZ;
    const float* qb = q + base + n;
    const float* kb = k + base;
    const float* vb = v + base;

    float qr[HDIM];
    #pragma unroll
    for (int c = 0; c < HDIM; c++) qr[c] = qb[(size_t)c * HWSZ];

    int nn[9];
    #pragma unroll
    for (int t = 0; t < 9; t++) {
        int yy = py + (t / 3 - 1) * dil;
        int xx = px + (t % 3 - 1) * dil;
        nn[t] = (yy >= 0 && yy < HH && xx >= 0 && xx < WW) ? (yy * WW + xx) : -1;
    }

    float logit[9];
    #pragma unroll
    for (int t = 0; t < 9; t++) {
        float acc = 0.f;
        if (nn[t] >= 0) {
            #pragma unroll
            for (int c = 0; c < HDIM; c++)
                acc += qr[c] * kb[(size_t)c * HWSZ + nn[t]];
        }
        logit[t] = acc * 0.17677669529663687f;   // 1/sqrt(32)
    }

    float mx = logit[0];
    #pragma unroll
    for (int t = 1; t < 9; t++) mx = fmaxf(mx, logit[t]);
    float s = 0.f;
    #pragma unroll
    for (int t = 0; t < 9; t++) { logit[t] = __expf(logit[t] - mx); s += logit[t]; }
    const float inv = 1.f / s;
    #pragma unroll
    for (int t = 0; t < 9; t++) logit[t] *= inv;

    float* xrow = xo + ((size_t)(b * HWSZ + n)) * CH + head * HDIM;
    #pragma unroll
    for (int c0 = 0; c0 < HDIM; c0 += 4) {
        float o[4];
        #pragma unroll
        for (int u = 0; u < 4; u++) {
            float acc = 0.f;
            #pragma unroll
            for (int t = 0; t < 9; t++)
                if (nn[t] >= 0)
                    acc += logit[t] * vb[(size_t)(c0 + u) * HWSZ + nn[t]];
            o[u] = acc;
        }
        *(float4*)&xrow[c0] = make_float4(o[0], o[1], o[2], o[3]);
    }
}

// =====================================================================
// GEMM-NT for activations: C[m,n] = sum_k A[m,k]*Wt[n,k] + epilogue
// MODE 0: proj   -> +bias,             store [m,256] to Cout
// MODE 1: fc1    -> +bias, exact GELU, store [m,1024] to Cout
// MODE 2: fc2    -> +bias, +resid[m,n], store TRANSPOSED [B,C,H,W] to Cout
// =====================================================================
template<int MODE, int LDC>
__global__ void gemm_act(const float* __restrict__ A,
                         const float* __restrict__ Wt,
                         const float* __restrict__ bias,
                         float* __restrict__ Cout,
                         const float* __restrict__ resid,
                         int K)
{
    __shared__ float As[16][64];   // As[k][m]
    __shared__ float Bs[16][64];   // Bs[k][n]

    const int mT = blockIdx.x * 64;
    const int nT = blockIdx.y * 64;

    const int tid = threadIdx.x;
    const int tx  = tid & 15, ty = tid >> 4;
    const int lr  = tid >> 2;
    const int lc  = (tid & 3) * 4;

    float acc[4][4] = {};

    for (int kt = 0; kt < K; kt += 16) {
        float4 a4 = *(const float4*)&A [(size_t)(mT + lr) * K + kt + lc];
        As[lc+0][lr] = a4.x; As[lc+1][lr] = a4.y;
        As[lc+2][lr] = a4.z; As[lc+3][lr] = a4.w;
        float4 b4 = *(const float4*)&Wt[(size_t)(nT + lr) * K + kt + lc];
        Bs[lc+0][lr] = b4.x; Bs[lc+1][lr] = b4.y;
        Bs[lc+2][lr] = b4.z; Bs[lc+3][lr] = b4.w;
        __syncthreads();
        #pragma unroll
        for (int k = 0; k < 16; k++) {
            float4 a = *(const float4*)&As[k][ty * 4];
            float4 bb = *(const float4*)&Bs[k][tx * 4];
            float av[4] = {a.x, a.y, a.z, a.w};
            float bv[4] = {bb.x, bb.y, bb.z, bb.w};
            #pragma unroll
            for (int i = 0; i < 4; i++)
                #pragma unroll
                for (int j = 0; j < 4; j++)
                    acc[i][j] += av[i] * bv[j];
        }
        __syncthreads();
    }

    const int m0 = mT + ty * 4;
    const int o0 = nT + tx * 4;
    float bj[4];
    #pragma unroll
    for (int j = 0; j < 4; j++) bj[j] = bias[o0 + j];

    if (MODE == 0) {
        #pragma unroll
        for (int i = 0; i < 4; i++) {
            float4 o4 = make_float4(acc[i][0] + bj[0], acc[i][1] + bj[1],
                                    acc[i][2] + bj[2], acc[i][3] + bj[3]);
            *(float4*)&Cout[(size_t)(m0 + i) * LDC + o0] = o4;
        }
    } else if (MODE == 1) {
        #pragma unroll
        for (int i = 0; i < 4; i++) {
            float o[4];
            #pragma unroll
            for (int j = 0; j < 4; j++) {
                float vv = acc[i][j] + bj[j];
                o[j] = 0.5f * vv * (1.f + erff(vv * 0.70710678118654752f));
            }
            *(float4*)&Cout[(size_t)(m0 + i) * LDC + o0] =
                make_float4(o[0], o[1], o[2], o[3]);
        }
    } else {
        // fc2: bias + residual, then transposed store out[b,c,h,w]
        float vals[4][4];
        #pragma unroll
        for (int i = 0; i < 4; i++) {
            float4 r = *(const float4*)&resid[(size_t)(m0 + i) * CH + o0];
            float rv[4] = {r.x, r.y, r.z, r.w};
            #pragma unroll
            for (int j = 0; j < 4; j++)
                vals[i][j] = acc[i][j] + bj[j] + rv[j];
        }
        const int bb = m0 >> 12;        // token / 4096
        const int hw = m0 & 4095;       // aligned to 4 (m0 % 4 == 0)
        #pragma unroll
        for (int j = 0; j < 4; j++) {
            float4 o4 = make_float4(vals[0][j], vals[1][j], vals[2][j], vals[3][j]);
            *(float4*)&Cout[((size_t)bb * CH + o0 + j) * HWSZ + hw] = o4;
        }
    }
}

// =====================================================================
// LayerNorm over 256 channels. 1 warp = 1 token, 8 channels / lane.
// =====================================================================
__global__ void ln_kernel(const float* __restrict__ xp,
                          const float* __restrict__ w,
                          const float* __restrict__ bb,
                          float* __restrict__ out)
{
    const int warp = threadIdx.x >> 5;
    const int lane = threadIdx.x & 31;
    const int tok  = blockIdx.x * 8 + warp;
    const float* row = xp + (size_t)tok * CH;

    float4 v0 = *(const float4*)&row[lane * 8];
    float4 v1 = *(const float4*)&row[lane * 8 + 4];
    float va[8] = {v0.x, v0.y, v0.z, v0.w, v1.x, v1.y, v1.z, v1.w};

    float s = 0.f, sq = 0.f;
    #pragma unroll
    for (int u = 0; u < 8; u++) { s += va[u]; sq += va[u] * va[u]; }
    #pragma unroll
    for (int o = 16; o; o >>= 1) {
        s  += __shfl_xor_sync(0xffffffffu, s,  o);
        sq += __shfl_xor_sync(0xffffffffu, sq, o);
    }
    const float mean = s * (1.f / 256.f);
    const float var  = sq * (1.f / 256.f) - mean * mean;
    const float inv  = rsqrtf(var + 1e-5f);

    float* orow = out + (size_t)tok * CH;
    float ov[8];
    #pragma unroll
    for (int u = 0; u < 8; u++) {
        int ch = lane * 8 + u;
        ov[u] = (va[u] - mean) * inv * w[ch] + bb[ch];
    }
    *(float4*)&orow[lane * 8]     = make_float4(ov[0], ov[1], ov[2], ov[3]);
    *(float4*)&orow[lane * 8 + 4] = make_float4(ov[4], ov[5], ov[6], ov[7]);
}

// =====================================================================
extern "C" void kernel_launch(void* const* d_in, const int* in_sizes, int n_in,
                              void* d_out, int out_size)
{
    const float* sub    = (const float*)d_in[0];
    const float* ori    = (const float*)d_in[1];
    const float* wq     = (const float*)d_in[2];
    const float* wk     = (const float*)d_in[3];
    const float* wv     = (const float*)d_in[4];
    const float* proj_w = (const float*)d_in[5];
    const float* proj_b = (const float*)d_in[6];
    const float* ln_w   = (const float*)d_in[7];
    const float* ln_b   = (const float*)d_in[8];
    const float* fc1_w  = (const float*)d_in[9];
    const float* fc1_b  = (const float*)d_in[10];
    const float* fc2_w  = (const float*)d_in[11];
    const float* fc2_b  = (const float*)d_in[12];
    float* out = (float*)d_out;

    float *p_q, *p_k, *p_v, *p_x, *p_xp, *p_ln, *p_h;
    cudaGetSymbolAddress((void**)&p_q,  g_q);
    cudaGetSymbolAddress((void**)&p_k,  g_k);
    cudaGetSymbolAddress((void**)&p_v,  g_v);
    cudaGetSymbolAddress((void**)&p_x,  g_x);
    cudaGetSymbolAddress((void**)&p_xp, g_xp);
    cudaGetSymbolAddress((void**)&p_ln, g_ln);
    cudaGetSymbolAddress((void**)&p_h,  g_h);

    // QKV projections (channel-major output)
    dim3 gq(HWSZ / 64, CH / 64, BATCH);
    gemm_qkv<<<gq, 256>>>(wq, sub, p_q);
    gemm_qkv<<<gq, 256>>>(wk, ori, p_k);
    gemm_qkv<<<gq, 256>>>(wv, ori, p_v);

    // Multi-dilation local attention -> g_x [tok, 256]
    dim3 ga(HWSZ / 128, NHEAD, BATCH);
    attn_kernel<<<ga, 128>>>(p_q, p_k, p_v, p_x);

    // proj + bias -> g_xp
    dim3 gp(NTOK / 64, CH / 64);
    gemm_act<0, CH><<<gp, 256>>>(p_x, proj_w, proj_b, p_xp, nullptr, CH);

    // layernorm -> g_ln
    ln_kernel<<<NTOK / 8, 256>>>(p_xp, ln_w, ln_b, p_ln);

    // fc1 + bias + GELU -> g_h
    dim3 g1(NTOK / 64, HID / 64);
    gemm_act<1, HID><<<g1, 256>>>(p_ln, fc1_w, fc1_b, p_h, nullptr, CH);

    // fc2 + bias + residual, transposed store -> d_out [B,C,H,W]
    dim3 g2(NTOK / 64, CH / 64);
    gemm_act<2, CH><<<g2, 256>>>(p_h, fc2_w, fc2_b, out, p_xp, HID);
}

// round 2
// speedup vs baseline: 2.3316x; 2.3316x over previous
#include <cuda_runtime.h>
#include <math.h>

// ---------------- problem constants ----------------
#define BATCH   8
#define CH      256
#define HH      64
#define WW      64
#define HWSZ    (HH*WW)          // 4096
#define NTOK    (BATCH*HWSZ)     // 32768
#define HID     1024
#define NHEAD   8
#define HDIM    32

// ---------------- scratch (device globals: allowed) ----------------
__device__ float g_q [BATCH*CH*HWSZ];
__device__ float g_k [BATCH*CH*HWSZ];
__device__ float g_v [BATCH*CH*HWSZ];
__device__ float g_x [NTOK*CH];    // attention out, [tok, 256]
__device__ float g_xp[NTOK*CH];    // proj out (residual source)
__device__ float g_ln[NTOK*CH];    // layernorm out
__device__ float g_h [NTOK*HID];   // mlp hidden

// ---------------- tf32 helpers ----------------
__device__ __forceinline__ float cvtf(float x) {
    unsigned u;
    asm("cvt.rna.tf32.f32 %0, %1;" : "=r"(u) : "f"(x));
    return __uint_as_float(u);
}

__device__ __forceinline__ void mma_tf32(float c[4], const float a[4], const float b[2]) {
    asm volatile(
        "mma.sync.aligned.m16n8k8.row.col.f32.tf32.tf32.f32 "
        "{%0,%1,%2,%3}, {%4,%5,%6,%7}, {%8,%9}, {%0,%1,%2,%3};\n"
        : "+f"(c[0]), "+f"(c[1]), "+f"(c[2]), "+f"(c[3])
        : "r"(__float_as_uint(a[0])), "r"(__float_as_uint(a[1])),
          "r"(__float_as_uint(a[2])), "r"(__float_as_uint(a[3])),
          "r"(__float_as_uint(b[0])), "r"(__float_as_uint(b[1])));
}

// =====================================================================
// Tensor-core tf32 GEMM, CTA tile 128x128, 8 warps (warp = 32x64).
//
// MODE 3 (qkv, NN):  C[o,n] = W[o,k] * X[k,n] per batch (blockIdx.z)
//                    A=W row-major [256,256]; B=X [k][n] row stride HWSZ
//                    store C[o*HWSZ+n] (channel-major), no bias.
// MODE 0 (proj, NT): C[m,n] = A[m,k]*Wt[n,k] + bias -> [m,LDC]
// MODE 1 (fc1,  NT): same + exact GELU
// MODE 2 (fc2,  NT): same + bias + resid[m,n], transposed store [B,C,H,W]
// =====================================================================
template<int MODE, int KDIM, int LDC>
__global__ __launch_bounds__(256, 2)
void gemm_tc(const float* __restrict__ A, const float* __restrict__ B,
             const float* __restrict__ bias, float* __restrict__ C,
             const float* __restrict__ resid)
{
    // stride 136: 136 % 32 == 8 -> fragment k-groups hit disjoint bank octets
    __shared__ float As[16][136];   // As[k][m]
    __shared__ float Bs[16][136];   // Bs[k][n]

    const int nT = blockIdx.x * 128;
    const int mT = blockIdx.y * 128;
    const int bz = blockIdx.z;

    const float* Bptr = (MODE == 3) ? (B + (size_t)bz * CH * HWSZ) : B;

    const int tid  = threadIdx.x;
    const int lane = tid & 31;
    const int wid  = tid >> 5;
    const int wm   = wid & 3;     // warp m: 0..3  -> 32 rows each
    const int wn   = wid >> 2;    // warp n: 0..1  -> 64 cols each
    const int lq   = lane >> 2;   // 0..7
    const int lr   = lane & 3;    // 0..3

    // loader indices (transposed scatter for K-contiguous operands)
    const int ar = tid >> 1;          // row (m or n), 0..127
    const int ac = (tid & 1) * 8;     // k base: 0 or 8
    // NN B loader (qkv): direct rows
    const int bk = tid >> 4;          // 0..15
    const int bn = (tid & 15) * 8;    // 0..120

    float acc[2][8][4];
    #pragma unroll
    for (int i = 0; i < 2; i++)
        #pragma unroll
        for (int j = 0; j < 8; j++)
            #pragma unroll
            for (int u = 0; u < 4; u++) acc[i][j][u] = 0.f;

    float4 pa0, pa1, pb0, pb1;

    // --- prefetch chunk 0 ---
    {
        const float* p = A + (size_t)(mT + ar) * KDIM + ac;
        pa0 = *(const float4*)p;  pa1 = *(const float4*)(p + 4);
        if (MODE == 3) {
            const float* q = Bptr + (size_t)bk * HWSZ + nT + bn;
            pb0 = *(const float4*)q;  pb1 = *(const float4*)(q + 4);
        } else {
            const float* q = Bptr + (size_t)(nT + ar) * KDIM + ac;
            pb0 = *(const float4*)q;  pb1 = *(const float4*)(q + 4);
        }
    }

    for (int kt = 0; kt < KDIM; kt += 16) {
        // store prefetched chunk to smem (tf32-converted)
        As[ac+0][ar] = cvtf(pa0.x); As[ac+1][ar] = cvtf(pa0.y);
        As[ac+2][ar] = cvtf(pa0.z); As[ac+3][ar] = cvtf(pa0.w);
        As[ac+4][ar] = cvtf(pa1.x); As[ac+5][ar] = cvtf(pa1.y);
        As[ac+6][ar] = cvtf(pa1.z); As[ac+7][ar] = cvtf(pa1.w);
        if (MODE == 3) {
            float4 c0 = make_float4(cvtf(pb0.x), cvtf(pb0.y), cvtf(pb0.z), cvtf(pb0.w));
            float4 c1 = make_float4(cvtf(pb1.x), cvtf(pb1.y), cvtf(pb1.z), cvtf(pb1.w));
            *(float4*)&Bs[bk][bn]     = c0;
            *(float4*)&Bs[bk][bn + 4] = c1;
        } else {
            Bs[ac+0][ar] = cvtf(pb0.x); Bs[ac+1][ar] = cvtf(pb0.y);
            Bs[ac+2][ar] = cvtf(pb0.z); Bs[ac+3][ar] = cvtf(pb0.w);
            Bs[ac+4][ar] = cvtf(pb1.x); Bs[ac+5][ar] = cvtf(pb1.y);
            Bs[ac+6][ar] = cvtf(pb1.z); Bs[ac+7][ar] = cvtf(pb1.w);
        }
        __syncthreads();

        // prefetch next chunk while computing
        if (kt + 16 < KDIM) {
            const float* p = A + (size_t)(mT + ar) * KDIM + kt + 16 + ac;
            pa0 = *(const float4*)p;  pa1 = *(const float4*)(p + 4);
            if (MODE == 3) {
                const float* q = Bptr + (size_t)(kt + 16 + bk) * HWSZ + nT + bn;
                pb0 = *(const float4*)q;  pb1 = *(const float4*)(q + 4);
            } else {
                const float* q = Bptr + (size_t)(nT + ar) * KDIM + kt + 16 + ac;
                pb0 = *(const float4*)q;  pb1 = *(const float4*)(q + 4);
            }
        }

        #pragma unroll
        for (int kk = 0; kk < 16; kk += 8) {
            float af[2][4];
            #pragma unroll
            for (int mt = 0; mt < 2; mt++) {
                const int m = wm * 32 + mt * 16 + lq;
                af[mt][0] = As[kk + lr    ][m];
                af[mt][1] = As[kk + lr    ][m + 8];
                af[mt][2] = As[kk + lr + 4][m];
                af[mt][3] = As[kk + lr + 4][m + 8];
            }
            #pragma unroll
            for (int nt = 0; nt < 8; nt++) {
                const int n = wn * 64 + nt * 8 + lq;
                float bf[2];
                bf[0] = Bs[kk + lr    ][n];
                bf[1] = Bs[kk + lr + 4][n];
                mma_tf32(acc[0][nt], af[0], bf);
                mma_tf32(acc[1][nt], af[1], bf);
            }
        }
        __syncthreads();
    }

    // ---------------- epilogue ----------------
    #pragma unroll
    for (int mt = 0; mt < 2; mt++) {
        #pragma unroll
        for (int nt = 0; nt < 8; nt++) {
            const int m0 = mT + wm * 32 + mt * 16 + lq;
            const int n0 = nT + wn * 64 + nt * 8 + (lr << 1);
            const float* cc = acc[mt][nt];

            if (MODE == 3) {
                float* p = C + (size_t)bz * CH * HWSZ;
                *(float2*)&p[(size_t)m0 * HWSZ + n0]       = make_float2(cc[0], cc[1]);
                *(float2*)&p[(size_t)(m0 + 8) * HWSZ + n0] = make_float2(cc[2], cc[3]);
            } else if (MODE == 0) {
                float2 bb = *(const float2*)&bias[n0];
                *(float2*)&C[(size_t)m0 * LDC + n0] =
                    make_float2(cc[0] + bb.x, cc[1] + bb.y);
                *(float2*)&C[(size_t)(m0 + 8) * LDC + n0] =
                    make_float2(cc[2] + bb.x, cc[3] + bb.y);
            } else if (MODE == 1) {
                float2 bb = *(const float2*)&bias[n0];
                float v[4] = {cc[0] + bb.x, cc[1] + bb.y, cc[2] + bb.x, cc[3] + bb.y};
                #pragma unroll
                for (int u = 0; u < 4; u++)
                    v[u] = 0.5f * v[u] * (1.f + erff(v[u] * 0.70710678118654752f));
                *(float2*)&C[(size_t)m0 * LDC + n0]       = make_float2(v[0], v[1]);
                *(float2*)&C[(size_t)(m0 + 8) * LDC + n0] = make_float2(v[2], v[3]);
            } else {
                float2 bb = *(const float2*)&bias[n0];
                float2 r0 = *(const float2*)&resid[(size_t)m0 * CH + n0];
                float2 r1 = *(const float2*)&resid[(size_t)(m0 + 8) * CH + n0];
                const float v00 = cc[0] + bb.x + r0.x;
                const float v01 = cc[1] + bb.y + r0.y;
                const float v10 = cc[2] + bb.x + r1.x;
                const float v11 = cc[3] + bb.y + r1.y;
                const int bi  = m0 >> 12;     // token / 4096
                const int hw0 = m0 & 4095;
                C[((size_t)bi * CH + n0    ) * HWSZ + hw0    ] = v00;
                C[((size_t)bi * CH + n0 + 1) * HWSZ + hw0    ] = v01;
                C[((size_t)bi * CH + n0    ) * HWSZ + hw0 + 8] = v10;
                C[((size_t)bi * CH + n0 + 1) * HWSZ + hw0 + 8] = v11;
            }
        }
    }
}

// =====================================================================
// Dilated 3x3 local attention. 1 thread = (pixel, head). Unchanged.
// =====================================================================
__global__ void attn_kernel(const float* __restrict__ q,
                            const float* __restrict__ k,
                            const float* __restrict__ v,
                            float* __restrict__ xo)
{
    const int b    = blockIdx.z;
    const int head = blockIdx.y;
    const int n    = blockIdx.x * 128 + threadIdx.x;
    const int py   = n >> 6;
    const int px   = n & 63;
    const int dil  = (head >> 1) + 1;

    const size_t base = ((size_t)b * CH + head * HDIM) * HWSZ;
    const float* qb = q + base + n;
    const float* kb = k + base;
    const float* vb = v + base;

    float qr[HDIM];
    #pragma unroll
    for (int c = 0; c < HDIM; c++) qr[c] = qb[(size_t)c * HWSZ];

    int nn[9];
    #pragma unroll
    for (int t = 0; t < 9; t++) {
        int yy = py + (t / 3 - 1) * dil;
        int xx = px + (t % 3 - 1) * dil;
        nn[t] = (yy >= 0 && yy < HH && xx >= 0 && xx < WW) ? (yy * WW + xx) : -1;
    }

    float logit[9];
    #pragma unroll
    for (int t = 0; t < 9; t++) {
        float acc = 0.f;
        if (nn[t] >= 0) {
            #pragma unroll
            for (int c = 0; c < HDIM; c++)
                acc += qr[c] * kb[(size_t)c * HWSZ + nn[t]];
        }
        logit[t] = acc * 0.17677669529663687f;
    }

    float mx = logit[0];
    #pragma unroll
    for (int t = 1; t < 9; t++) mx = fmaxf(mx, logit[t]);
    float s = 0.f;
    #pragma unroll
    for (int t = 0; t < 9; t++) { logit[t] = __expf(logit[t] - mx); s += logit[t]; }
    const float inv = 1.f / s;
    #pragma unroll
    for (int t = 0; t < 9; t++) logit[t] *= inv;

    float* xrow = xo + ((size_t)(b * HWSZ + n)) * CH + head * HDIM;
    #pragma unroll
    for (int c0 = 0; c0 < HDIM; c0 += 4) {
        float o[4];
        #pragma unroll
        for (int u = 0; u < 4; u++) {
            float acc = 0.f;
            #pragma unroll
            for (int t = 0; t < 9; t++)
                if (nn[t] >= 0)
                    acc += logit[t] * vb[(size_t)(c0 + u) * HWSZ + nn[t]];
            o[u] = acc;
        }
        *(float4*)&xrow[c0] = make_float4(o[0], o[1], o[2], o[3]);
    }
}

// =====================================================================
// LayerNorm over 256 channels. 1 warp = 1 token. Unchanged.
// =====================================================================
__global__ void ln_kernel(const float* __restrict__ xp,
                          const float* __restrict__ w,
                          const float* __restrict__ bb,
                          float* __restrict__ out)
{
    const int warp = threadIdx.x >> 5;
    const int lane = threadIdx.x & 31;
    const int tok  = blockIdx.x * 8 + warp;
    const float* row = xp + (size_t)tok * CH;

    float4 v0 = *(const float4*)&row[lane * 8];
    float4 v1 = *(const float4*)&row[lane * 8 + 4];
    float va[8] = {v0.x, v0.y, v0.z, v0.w, v1.x, v1.y, v1.z, v1.w};

    float s = 0.f, sq = 0.f;
    #pragma unroll
    for (int u = 0; u < 8; u++) { s += va[u]; sq += va[u] * va[u]; }
    #pragma unroll
    for (int o = 16; o; o >>= 1) {
        s  += __shfl_xor_sync(0xffffffffu, s,  o);
        sq += __shfl_xor_sync(0xffffffffu, sq, o);
    }
    const float mean = s * (1.f / 256.f);
    const float var  = sq * (1.f / 256.f) - mean * mean;
    const float inv  = rsqrtf(var + 1e-5f);

    float* orow = out + (size_t)tok * CH;
    float ov[8];
    #pragma unroll
    for (int u = 0; u < 8; u++) {
        int ch = lane * 8 + u;
        ov[u] = (va[u] - mean) * inv * w[ch] + bb[ch];
    }
    *(float4*)&orow[lane * 8]     = make_float4(ov[0], ov[1], ov[2], ov[3]);
    *(float4*)&orow[lane * 8 + 4] = make_float4(ov[4], ov[5], ov[6], ov[7]);
}

// =====================================================================
extern "C" void kernel_launch(void* const* d_in, const int* in_sizes, int n_in,
                              void* d_out, int out_size)
{
    const float* sub    = (const float*)d_in[0];
    const float* ori    = (const float*)d_in[1];
    const float* wq     = (const float*)d_in[2];
    const float* wk     = (const float*)d_in[3];
    const float* wv     = (const float*)d_in[4];
    const float* proj_w = (const float*)d_in[5];
    const float* proj_b = (const float*)d_in[6];
    const float* ln_w   = (const float*)d_in[7];
    const float* ln_b   = (const float*)d_in[8];
    const float* fc1_w  = (const float*)d_in[9];
    const float* fc1_b  = (const float*)d_in[10];
    const float* fc2_w  = (const float*)d_in[11];
    const float* fc2_b  = (const float*)d_in[12];
    float* out = (float*)d_out;

    float *p_q, *p_k, *p_v, *p_x, *p_xp, *p_ln, *p_h;
    cudaGetSymbolAddress((void**)&p_q,  g_q);
    cudaGetSymbolAddress((void**)&p_k,  g_k);
    cudaGetSymbolAddress((void**)&p_v,  g_v);
    cudaGetSymbolAddress((void**)&p_x,  g_x);
    cudaGetSymbolAddress((void**)&p_xp, g_xp);
    cudaGetSymbolAddress((void**)&p_ln, g_ln);
    cudaGetSymbolAddress((void**)&p_h,  g_h);

    // QKV projections (tf32 tensor cores, channel-major output)
    dim3 gq(HWSZ / 128, CH / 128, BATCH);           // (32, 2, 8)
    gemm_tc<3, CH, 0><<<gq, 256>>>(wq, sub, nullptr, p_q, nullptr);
    gemm_tc<3, CH, 0><<<gq, 256>>>(wk, ori, nullptr, p_k, nullptr);
    gemm_tc<3, CH, 0><<<gq, 256>>>(wv, ori, nullptr, p_v, nullptr);

    // Multi-dilation local attention -> g_x [tok, 256]
    dim3 ga(HWSZ / 128, NHEAD, BATCH);
    attn_kernel<<<ga, 128>>>(p_q, p_k, p_v, p_x);

    // proj + bias -> g_xp
    dim3 gp(CH / 128, NTOK / 128, 1);               // (2, 256)
    gemm_tc<0, CH, CH><<<gp, 256>>>(p_x, proj_w, proj_b, p_xp, nullptr);

    // layernorm -> g_ln
    ln_kernel<<<NTOK / 8, 256>>>(p_xp, ln_w, ln_b, p_ln);

    // fc1 + bias + GELU -> g_h
    dim3 g1(HID / 128, NTOK / 128, 1);              // (8, 256)
    gemm_tc<1, CH, HID><<<g1, 256>>>(p_ln, fc1_w, fc1_b, p_h, nullptr);

    // fc2 + bias + residual, transposed store -> d_out [B,C,H,W]
    dim3 g2(CH / 128, NTOK / 128, 1);               // (2, 256)
    gemm_tc<2, HID, CH><<<g2, 256>>>(p_h, fc2_w, fc2_b, out, p_xp);
}

// round 4
// speedup vs baseline: 3.6193x; 1.5523x over previous
#include <cuda_runtime.h>
#include <math.h>
#include <stdint.h>

// ---------------- problem constants ----------------
#define BATCH   8
#define CH      256
#define HH      64
#define WW      64
#define HWSZ    (HH*WW)          // 4096
#define NTOK    (BATCH*HWSZ)     // 32768
#define HID     1024
#define NHEAD   8
#define HDIM    32

// ---------------- scratch ----------------
__device__ float g_ts[NTOK*CH];    // sub transposed [tok][c] (tf32)
__device__ float g_to[NTOK*CH];    // ori transposed [tok][c] (tf32)
__device__ float g_q [BATCH*CH*HWSZ];
__device__ float g_k [BATCH*CH*HWSZ];
__device__ float g_v [BATCH*CH*HWSZ];
__device__ float g_x [NTOK*CH];    // attention out (tf32), [tok,256]
__device__ float g_xp[NTOK*CH];    // proj out fp32 (residual)
__device__ float g_ln[NTOK*CH];    // layernorm out (tf32)
__device__ float g_h [NTOK*HID];   // mlp hidden (tf32)
__device__ float g_wq[CH*CH];      // tf32-rounded weights
__device__ float g_wk[CH*CH];
__device__ float g_wv[CH*CH];
__device__ float g_wp[CH*CH];
__device__ float g_w1[HID*CH];
__device__ float g_w2[CH*HID];

// ---------------- helpers ----------------
__device__ __forceinline__ float cvtf(float x) {
    unsigned u;
    asm("cvt.rna.tf32.f32 %0, %1;" : "=r"(u) : "f"(x));
    return __uint_as_float(u);
}
__device__ __forceinline__ uint32_t smem_u32(const void* p) {
    uint32_t a;
    asm("{ .reg .u64 t; cvta.to.shared.u64 t, %1; cvt.u32.u64 %0, t; }"
        : "=r"(a) : "l"(p));
    return a;
}
__device__ __forceinline__ void cp16(uint32_t s, const void* g) {
    asm volatile("cp.async.cg.shared.global [%0], [%1], 16;" :: "r"(s), "l"(g));
}
#define CP_COMMIT() asm volatile("cp.async.commit_group;" ::: "memory")
#define CP_WAIT1()  asm volatile("cp.async.wait_group 1;" ::: "memory")

__device__ __forceinline__ void ldsm_x4(uint32_t r[4], uint32_t addr) {
    asm volatile("ldmatrix.sync.aligned.m8n8.x4.shared.b16 {%0,%1,%2,%3}, [%4];"
        : "=r"(r[0]), "=r"(r[1]), "=r"(r[2]), "=r"(r[3]) : "r"(addr));
}
__device__ __forceinline__ void mma_tf32(float c[4], const uint32_t a[4],
                                         uint32_t b0, uint32_t b1) {
    asm volatile(
        "mma.sync.aligned.m16n8k8.row.col.f32.tf32.tf32.f32 "
        "{%0,%1,%2,%3}, {%4,%5,%6,%7}, {%8,%9}, {%0,%1,%2,%3};\n"
        : "+f"(c[0]), "+f"(c[1]), "+f"(c[2]), "+f"(c[3])
        : "r"(a[0]), "r"(a[1]), "r"(a[2]), "r"(a[3]), "r"(b0), "r"(b1));
}

// =====================================================================
// Unified tf32 NT GEMM: C[m,n] = sum_k A[m,k] * W[n,k] + epilogue
// CTA 128x128, K-chunk 32, 2-stage cp.async, ldmatrix fragments.
// Smem layout per operand: 128 rows x 128B (32 floats), swizzled
//   addr(row, q16) = base + row*128 + ((q16 ^ (row&7)) * 16)
// MODE 4: qkv  -> no bias, transposed store to [B][CH][HWSZ]
// MODE 0: proj -> +bias, store fp32 [m][LDC]
// MODE 1: fc1  -> +bias, exact GELU, cvtf, store [m][LDC]
// MODE 2: fc2  -> +bias +resid[m][n], transposed store [B][CH][HWSZ]
// =====================================================================
#define STAGE_B 32768   // 16KB A + 16KB B
#define SMEM_SZ (2*STAGE_B)

template<int MODE, int KDIM, int LDC>
__global__ __launch_bounds__(256, 2)
void gemm_nt(const float* __restrict__ A, const float* __restrict__ Wt,
             const float* __restrict__ bias, float* __restrict__ Cout,
             const float* __restrict__ resid)
{
    extern __shared__ __align__(128) char smem[];
    const uint32_t sb = smem_u32(smem);

    const int tid  = threadIdx.x;
    const int lane = tid & 31;
    const int wid  = tid >> 5;
    const int wm   = wid & 3;      // m: 32-row block
    const int wn   = wid >> 2;     // n: 64-col block
    const int lq   = lane >> 2;
    const int lr   = lane & 3;

    const int nT = blockIdx.x * 128;
    const int mT = blockIdx.y * 128;
    const int NCH = KDIM / 32;

    // ldmatrix per-thread row assignments
    // A (per mt tile): row = wm*32 + mt*16 + (lane & 15), q16 = q0 + (lane>>4)
    const int arow  = wm * 32 + (lane & 15);
    const int aqsel = lane >> 4;
    const uint32_t abase0 = (uint32_t)arow * 128;
    const uint32_t abase1 = (uint32_t)(arow + 16) * 128;
    const int axor0 = arow & 7;
    const int axor1 = (arow + 16) & 7;   // == axor0, but keep explicit
    // B (per nt2 group): row = wn*64 + nt2*16 + (lane&7) + (lane>>4)*8
    const int brow  = wn * 64 + (lane & 7) + ((lane >> 4) << 3);
    const int bqsel = (lane >> 3) & 1;

    float acc[2][8][4];
    #pragma unroll
    for (int i = 0; i < 2; i++)
        #pragma unroll
        for (int j = 0; j < 8; j++)
            #pragma unroll
            for (int u = 0; u < 4; u++) acc[i][j][u] = 0.f;

    // ---- stage loader ----
    auto load_stage = [&](int s, int kt) {
        const uint32_t ab = sb + s * STAGE_B;
        const uint32_t bb = ab + 16384;
        #pragma unroll
        for (int j = 0; j < 4; j++) {
            int c = tid + j * 256;          // 0..1023
            int row = c >> 3, q = c & 7;
            uint32_t off = (uint32_t)row * 128 + (uint32_t)((q ^ (row & 7)) * 16);
            cp16(ab + off, A  + (size_t)(mT + row) * KDIM + kt + q * 4);
            cp16(bb + off, Wt + (size_t)(nT + row) * KDIM + kt + q * 4);
        }
    };

    load_stage(0, 0);  CP_COMMIT();
    load_stage(1, 32); CP_COMMIT();

    for (int it = 0; it < NCH; it++) {
        const int s = it & 1;
        CP_WAIT1();
        __syncthreads();

        const uint32_t ab = sb + s * STAGE_B;
        const uint32_t bb = ab + 16384;

        #pragma unroll
        for (int kk = 0; kk < 4; kk++) {
            const int q0 = kk * 2;
            uint32_t af[2][4];
            {
                const int qa = q0 + aqsel;
                ldsm_x4(af[0], ab + abase0 + (uint32_t)((qa ^ axor0) * 16));
                ldsm_x4(af[1], ab + abase1 + (uint32_t)((qa ^ axor1) * 16));
            }
            #pragma unroll
            for (int nt2 = 0; nt2 < 4; nt2++) {
                const int row = brow + nt2 * 16;
                const int qb = q0 + bqsel;
                uint32_t bf[4];
                ldsm_x4(bf, bb + (uint32_t)row * 128 + (uint32_t)((qb ^ (row & 7)) * 16));
                mma_tf32(acc[0][nt2*2  ], af[0], bf[0], bf[1]);
                mma_tf32(acc[0][nt2*2+1], af[0], bf[2], bf[3]);
                mma_tf32(acc[1][nt2*2  ], af[1], bf[0], bf[1]);
                mma_tf32(acc[1][nt2*2+1], af[1], bf[2], bf[3]);
            }
        }
        __syncthreads();
        if (it + 2 < NCH) load_stage(s, (it + 2) * 32);
        CP_COMMIT();
    }

    // ---------------- epilogue ----------------
    #pragma unroll
    for (int mt = 0; mt < 2; mt++) {
        #pragma unroll
        for (int idx = 0; idx < 8; idx++) {
            const int nt2 = idx >> 1, tt = idx & 1;
            const int m0 = mT + wm * 32 + mt * 16 + lq;
            const int n0 = nT + wn * 64 + nt2 * 16 + tt * 8 + (lr << 1);
            const float* cc = acc[mt][idx];

            if (MODE == 4) {
                // qkv: transposed store, no bias
                const int bi = m0 >> 12;
                const int hw = m0 & 4095;
                float* p = Cout + (size_t)bi * CH * HWSZ;
                p[(size_t)(n0    ) * HWSZ + hw    ] = cc[0];
                p[(size_t)(n0 + 1) * HWSZ + hw    ] = cc[1];
                p[(size_t)(n0    ) * HWSZ + hw + 8] = cc[2];
                p[(size_t)(n0 + 1) * HWSZ + hw + 8] = cc[3];
            } else if (MODE == 0) {
                float2 bv = *(const float2*)&bias[n0];
                *(float2*)&Cout[(size_t)m0 * LDC + n0] =
                    make_float2(cc[0] + bv.x, cc[1] + bv.y);
                *(float2*)&Cout[(size_t)(m0 + 8) * LDC + n0] =
                    make_float2(cc[2] + bv.x, cc[3] + bv.y);
            } else if (MODE == 1) {
                float2 bv = *(const float2*)&bias[n0];
                float v[4] = {cc[0] + bv.x, cc[1] + bv.y, cc[2] + bv.x, cc[3] + bv.y};
                #pragma unroll
                for (int u = 0; u < 4; u++)
                    v[u] = cvtf(0.5f * v[u] * (1.f + erff(v[u] * 0.70710678118654752f)));
                *(float2*)&Cout[(size_t)m0 * LDC + n0]       = make_float2(v[0], v[1]);
                *(float2*)&Cout[(size_t)(m0 + 8) * LDC + n0] = make_float2(v[2], v[3]);
            } else {
                float2 bv = *(const float2*)&bias[n0];
                float2 r0 = *(const float2*)&resid[(size_t)m0 * CH + n0];
                float2 r1 = *(const float2*)&resid[(size_t)(m0 + 8) * CH + n0];
                const int bi = m0 >> 12;
                const int hw = m0 & 4095;
                float* p = Cout + (size_t)bi * CH * HWSZ;
                p[(size_t)(n0    ) * HWSZ + hw    ] = cc[0] + bv.x + r0.x;
                p[(size_t)(n0 + 1) * HWSZ + hw    ] = cc[1] + bv.y + r0.y;
                p[(size_t)(n0    ) * HWSZ + hw + 8] = cc[2] + bv.x + r1.x;
                p[(size_t)(n0 + 1) * HWSZ + hw + 8] = cc[3] + bv.y + r1.y;
            }
        }
    }
}

// =====================================================================
// Tiled transpose + tf32 round: [b][256][4096] -> [b*4096][256]
// =====================================================================
__global__ void transpose_cvt(const float* __restrict__ in, float* __restrict__ out)
{
    __shared__ float t[32][33];
    const int b  = blockIdx.z;
    const int p0 = blockIdx.x * 32;   // hw tile
    const int c0 = blockIdx.y * 32;   // channel tile
    const int tx = threadIdx.x, ty = threadIdx.y;   // 32 x 8
    const float* ib = in + (size_t)b * CH * HWSZ;
    float* ob = out + (size_t)b * HWSZ * CH;
    #pragma unroll
    for (int i = 0; i < 4; i++)
        t[ty + 8*i][tx] = ib[(size_t)(c0 + ty + 8*i) * HWSZ + p0 + tx];
    __syncthreads();
    #pragma unroll
    for (int i = 0; i < 4; i++)
        ob[(size_t)(p0 + ty + 8*i) * CH + c0 + tx] = cvtf(t[tx][ty + 8*i]);
}

// =====================================================================
// Dilated 3x3 local attention. 1 thread = (pixel, head).
// =====================================================================
__global__ void attn_kernel(const float* __restrict__ q,
                            const float* __restrict__ k,
                            const float* __restrict__ v,
                            float* __restrict__ xo)
{
    const int b    = blockIdx.z;
    const int head = blockIdx.y;
    const int n    = blockIdx.x * 128 + threadIdx.x;
    const int py   = n >> 6;
    const int px   = n & 63;
    const int dil  = (head >> 1) + 1;

    const size_t base = ((size_t)b * CH + head * HDIM) * HWSZ;
    const float* qb = q + base + n;
    const float* kb = k + base;
    const float* vb = v + base;

    float qr[HDIM];
    #pragma unroll
    for (int c = 0; c < HDIM; c++) qr[c] = qb[(size_t)c * HWSZ];

    int nn[9];
    #pragma unroll
    for (int t = 0; t < 9; t++) {
        int yy = py + (t / 3 - 1) * dil;
        int xx = px + (t % 3 - 1) * dil;
        nn[t] = (yy >= 0 && yy < HH && xx >= 0 && xx < WW) ? (yy * WW + xx) : -1;
    }

    float logit[9];
    #pragma unroll
    for (int t = 0; t < 9; t++) {
        float acc = 0.f;
        if (nn[t] >= 0) {
            #pragma unroll
            for (int c = 0; c < HDIM; c++)
                acc += qr[c] * kb[(size_t)c * HWSZ + nn[t]];
        }
        logit[t] = acc * 0.17677669529663687f;
    }

    float mx = logit[0];
    #pragma unroll
    for (int t = 1; t < 9; t++) mx = fmaxf(mx, logit[t]);
    float s = 0.f;
    #pragma unroll
    for (int t = 0; t < 9; t++) { logit[t] = __expf(logit[t] - mx); s += logit[t]; }
    const float inv = 1.f / s;
    #pragma unroll
    for (int t = 0; t < 9; t++) logit[t] *= inv;

    float* xrow = xo + ((size_t)(b * HWSZ + n)) * CH + head * HDIM;
    #pragma unroll
    for (int c0 = 0; c0 < HDIM; c0 += 4) {
        float o[4];
        #pragma unroll
        for (int u = 0; u < 4; u++) {
            float acc = 0.f;
            #pragma unroll
            for (int t = 0; t < 9; t++)
                if (nn[t] >= 0)
                    acc += logit[t] * vb[(size_t)(c0 + u) * HWSZ + nn[t]];
            o[u] = cvtf(acc);
        }
        *(float4*)&xrow[c0] = make_float4(o[0], o[1], o[2], o[3]);
    }
}

// =====================================================================
// LayerNorm over 256 channels. 1 warp = 1 token.
// =====================================================================
__global__ void ln_kernel(const float* __restrict__ xp,
                          const float* __restrict__ w,
                          const float* __restrict__ bb,
                          float* __restrict__ out)
{
    const int warp = threadIdx.x >> 5;
    const int lane = threadIdx.x & 31;
    const int tok  = blockIdx.x * 8 + warp;
    const float* row = xp + (size_t)tok * CH;

    float4 v0 = *(const float4*)&row[lane * 8];
    float4 v1 = *(const float4*)&row[lane * 8 + 4];
    float va[8] = {v0.x, v0.y, v0.z, v0.w, v1.x, v1.y, v1.z, v1.w};

    float s = 0.f, sq = 0.f;
    #pragma unroll
    for (int u = 0; u < 8; u++) { s += va[u]; sq += va[u] * va[u]; }
    #pragma unroll
    for (int o = 16; o; o >>= 1) {
        s  += __shfl_xor_sync(0xffffffffu, s,  o);
        sq += __shfl_xor_sync(0xffffffffu, sq, o);
    }
    const float mean = s * (1.f / 256.f);
    const float var  = sq * (1.f / 256.f) - mean * mean;
    const float inv  = rsqrtf(var + 1e-5f);

    float* orow = out + (size_t)tok * CH;
    float ov[8];
    #pragma unroll
    for (int u = 0; u < 8; u++) {
        int ch = lane * 8 + u;
        ov[u] = cvtf((va[u] - mean) * inv * w[ch] + bb[ch]);
    }
    *(float4*)&orow[lane * 8]     = make_float4(ov[0], ov[1], ov[2], ov[3]);
    *(float4*)&orow[lane * 8 + 4] = make_float4(ov[4], ov[5], ov[6], ov[7]);
}

// ---------------- weight pre-round (rna -> tf32) ----------------
__global__ void round_w(const float* __restrict__ a, float* __restrict__ b, int n)
{
    int i = blockIdx.x * 256 + threadIdx.x;
    if (i < n) b[i] = cvtf(a[i]);
}

// =====================================================================
extern "C" void kernel_launch(void* const* d_in, const int* in_sizes, int n_in,
                              void* d_out, int out_size)
{
    const float* sub    = (const float*)d_in[0];
    const float* ori    = (const float*)d_in[1];
    const float* wq     = (const float*)d_in[2];
    const float* wk     = (const float*)d_in[3];
    const float* wv     = (const float*)d_in[4];
    const float* proj_w = (const float*)d_in[5];
    const float* proj_b = (const float*)d_in[6];
    const float* ln_w   = (const float*)d_in[7];
    const float* ln_b   = (const float*)d_in[8];
    const float* fc1_w  = (const float*)d_in[9];
    const float* fc1_b  = (const float*)d_in[10];
    const float* fc2_w  = (const float*)d_in[11];
    const float* fc2_b  = (const float*)d_in[12];
    float* out = (float*)d_out;

    float *p_ts, *p_to, *p_q, *p_k, *p_v, *p_x, *p_xp, *p_ln, *p_h;
    float *p_wq, *p_wk, *p_wv, *p_wp, *p_w1, *p_w2;
    cudaGetSymbolAddress((void**)&p_ts, g_ts);
    cudaGetSymbolAddress((void**)&p_to, g_to);
    cudaGetSymbolAddress((void**)&p_q,  g_q);
    cudaGetSymbolAddress((void**)&p_k,  g_k);
    cudaGetSymbolAddress((void**)&p_v,  g_v);
    cudaGetSymbolAddress((void**)&p_x,  g_x);
    cudaGetSymbolAddress((void**)&p_xp, g_xp);
    cudaGetSymbolAddress((void**)&p_ln, g_ln);
    cudaGetSymbolAddress((void**)&p_h,  g_h);
    cudaGetSymbolAddress((void**)&p_wq, g_wq);
    cudaGetSymbolAddress((void**)&p_wk, g_wk);
    cudaGetSymbolAddress((void**)&p_wv, g_wv);
    cudaGetSymbolAddress((void**)&p_wp, g_wp);
    cudaGetSymbolAddress((void**)&p_w1, g_w1);
    cudaGetSymbolAddress((void**)&p_w2, g_w2);

    cudaFuncSetAttribute(gemm_nt<4, CH,  0  >, cudaFuncAttributeMaxDynamicSharedMemorySize, SMEM_SZ);
    cudaFuncSetAttribute(gemm_nt<0, CH,  CH >, cudaFuncAttributeMaxDynamicSharedMemorySize, SMEM_SZ);
    cudaFuncSetAttribute(gemm_nt<1, CH,  HID>, cudaFuncAttributeMaxDynamicSharedMemorySize, SMEM_SZ);
    cudaFuncSetAttribute(gemm_nt<2, HID, CH >, cudaFuncAttributeMaxDynamicSharedMemorySize, SMEM_SZ);

    // weight pre-rounding
    round_w<<<(CH*CH  + 255) / 256, 256>>>(wq,     p_wq, CH*CH);
    round_w<<<(CH*CH  + 255) / 256, 256>>>(wk,     p_wk, CH*CH);
    round_w<<<(CH*CH  + 255) / 256, 256>>>(wv,     p_wv, CH*CH);
    round_w<<<(CH*CH  + 255) / 256, 256>>>(proj_w, p_wp, CH*CH);
    round_w<<<(HID*CH + 255) / 256, 256>>>(fc1_w,  p_w1, HID*CH);
    round_w<<<(CH*HID + 255) / 256, 256>>>(fc2_w,  p_w2, CH*HID);

    // transpose inputs to [tok][c] with tf32 rounding
    dim3 gt(HWSZ / 32, CH / 32, BATCH);
    dim3 bt(32, 8);
    transpose_cvt<<<gt, bt>>>(sub, p_ts);
    transpose_cvt<<<gt, bt>>>(ori, p_to);

    // qkv (NT, transposed store to channel-major)
    dim3 gq(CH / 128, NTOK / 128);       // (2, 256)
    gemm_nt<4, CH, 0><<<gq, 256, SMEM_SZ>>>(p_ts, p_wq, nullptr, p_q, nullptr);
    gemm_nt<4, CH, 0><<<gq, 256, SMEM_SZ>>>(p_to, p_wk, nullptr, p_k, nullptr);
    gemm_nt<4, CH, 0><<<gq, 256, SMEM_SZ>>>(p_to, p_wv, nullptr, p_v, nullptr);

    // attention -> g_x [tok][256] (tf32)
    dim3 ga(HWSZ / 128, NHEAD, BATCH);
    attn_kernel<<<ga, 128>>>(p_q, p_k, p_v, p_x);

    // proj + bias -> g_xp
    dim3 gp(CH / 128, NTOK / 128);
    gemm_nt<0, CH, CH><<<gp, 256, SMEM_SZ>>>(p_x, p_wp, proj_b, p_xp, nullptr);

    // layernorm -> g_ln (tf32)
    ln_kernel<<<NTOK / 8, 256>>>(p_xp, ln_w, ln_b, p_ln);

    // fc1 + bias + GELU -> g_h (tf32)
    dim3 g1(HID / 128, NTOK / 128);
    gemm_nt<1, CH, HID><<<g1, 256, SMEM_SZ>>>(p_ln, p_w1, fc1_b, p_h, nullptr);

    // fc2 + bias + residual, transposed store -> d_out [B][C][H][W]
    dim3 g2(CH / 128, NTOK / 128);
    gemm_nt<2, HID, CH><<<g2, 256, SMEM_SZ>>>(p_h, p_w2, fc2_b, out, p_xp);
}